// round 3
// baseline (speedup 1.0000x reference)
#include <cuda_runtime.h>
#include <math.h>
#include <stdint.h>

#define Bb 8
#define Cc 1536
#define Tt 4096
#define Aa 128
#define K3 (3*Cc)   // 4608
#define BN 64
#define BK 16

// Scratch (allocation-free rule: __device__ globals)
static __device__ float g_mean[(size_t)Bb*Cc*Tt];
static __device__ float g_std [(size_t)Bb*Cc*Tt];
static __device__ float g_logits[Bb*Tt];
static __device__ float g_e[Bb*Tt];
static __device__ float g_Z[Bb*Tt];

// Robust lengths read: reference asked for int64, but JAX without x64 silently
// produces int32. Detect layout from the first 32 bytes (safe in both cases):
// int64 little-endian -> odd int32 words are 0 (lengths are in [2048,4096]);
// int32 -> odd words are >= 2048.
__device__ __forceinline__ int load_length(const void* lp, int b)
{
    const int* w = (const int*)lp;
    bool is64 = true;
#pragma unroll
    for (int i = 0; i < 4; i++)
        if (w[2*i + 1] != 0) is64 = false;
    if (is64) return (int)((const long long*)lp)[b];
    return w[b];
}

// Exclusive block scan over 256 per-thread values. ws: >= 8 floats smem.
__device__ __forceinline__ float block_excl_scan256(float v, float* ws)
{
    int lane = threadIdx.x & 31;
    int warp = threadIdx.x >> 5;
    float incl = v;
#pragma unroll
    for (int d = 1; d < 32; d <<= 1) {
        float n = __shfl_up_sync(0xffffffffu, incl, d);
        if (lane >= d) incl += n;
    }
    __syncthreads();
    if (lane == 31) ws[warp] = incl;
    __syncthreads();
    if (warp == 0) {
        float wv = (lane < 8) ? ws[lane] : 0.f;
        float wi = wv;
#pragma unroll
        for (int d = 1; d < 8; d <<= 1) {
            float n = __shfl_up_sync(0xffffffffu, wi, d);
            if (lane >= d) wi += n;
        }
        if (lane < 8) ws[lane] = wi - wv;   // exclusive warp offsets
    }
    __syncthreads();
    return ws[warp] + (incl - v);
}

// ---------------- Kernel 1: causal mean / std ----------------
__global__ void __launch_bounds__(256) stats_kernel(const float* __restrict__ x,
                                                    const void* __restrict__ lengths)
{
    int c = blockIdx.x, b = blockIdx.y;
    size_t roff = ((size_t)b*Cc + c)*(size_t)Tt;
    const float4* row4 = (const float4*)(x + roff);
    float4* m4 = (float4*)(g_mean + roff);
    float4* s4 = (float4*)(g_std  + roff);
    int len = load_length(lengths, b);
    __shared__ float ws[8];
    int tid = threadIdx.x;
    int base = tid * 16;

    float xv[16];
#pragma unroll
    for (int q = 0; q < 4; q++) {
        float4 f = row4[tid*4 + q];
        xv[q*4+0]=f.x; xv[q*4+1]=f.y; xv[q*4+2]=f.z; xv[q*4+3]=f.w;
    }
    float l1[16], l2[16];
    float c1 = 0.f, c2 = 0.f;
#pragma unroll
    for (int j = 0; j < 16; j++) {
        int t = base + j;
        float v = (t < len) ? xv[j] : 0.f;
        c1 += v; c2 += v*v;
        l1[j] = c1; l2[j] = c2;
    }
    float o1 = block_excl_scan256(c1, ws);
    float o2 = block_excl_scan256(c2, ws);

    float mv[16], sv[16];
#pragma unroll
    for (int j = 0; j < 16; j++) {
        int t = base + j;
        int cn = (t + 1 < len) ? (t + 1) : len;
        float cnt = (cn < 1) ? 1.f : (float)cn;
        float m = (o1 + l1[j]) / cnt;
        float var = (o2 + l2[j]) / cnt - m*m;
        mv[j] = m;
        sv[j] = sqrtf(fmaxf(var, 1e-12f));
    }
#pragma unroll
    for (int q = 0; q < 4; q++) {
        m4[tid*4+q] = make_float4(mv[q*4], mv[q*4+1], mv[q*4+2], mv[q*4+3]);
        s4[tid*4+q] = make_float4(sv[q*4], sv[q*4+1], sv[q*4+2], sv[q*4+3]);
    }
}

// ---------------- Kernel 2: logits = W2 . tanh(W1 @ [x;mean;std] + b1) + b2 ----------------
// Tiled fp32 GEMM: BM=128 (all A rows), BN=64 t-cols, BK=16. 256 threads, 8x4 reg tile.
__global__ void __launch_bounds__(256) logits_kernel(const float* __restrict__ x,
                                                     const float* __restrict__ W1,
                                                     const float* __restrict__ b1,
                                                     const float* __restrict__ W2,
                                                     const float* __restrict__ b2)
{
    int b  = blockIdx.y;
    int t0 = blockIdx.x * BN;
    __shared__ float Ws[BK][Aa + 1];   // +1 pad: kills 16-way store conflicts
    __shared__ float As[BK][BN];
    __shared__ float red[16][BN];

    int tid = threadIdx.x;
    int tx = tid & 15;    // t group (4 cols each)
    int ty = tid >> 4;    // a group (8 rows each)

    int wkk  = tid & 15;  // W-load: column within tile
    int wa0  = tid >> 4;  // W-load: starting row
    int acol = tid & 63;  // attn-load: t column
    int akk0 = tid >> 6;  // attn-load: starting k row (0..3)

    float acc[8][4];
#pragma unroll
    for (int i = 0; i < 8; i++)
#pragma unroll
        for (int j = 0; j < 4; j++) acc[i][j] = 0.f;

    for (int kt = 0; kt < K3/BK; kt++) {
        int k0 = kt * BK;
        // W1 tile (128 x 16)
#pragma unroll
        for (int r = 0; r < 8; r++) {
            int a = wa0 + 16*r;
            Ws[wkk][a] = W1[(size_t)a*K3 + k0 + wkk];
        }
        // attn tile (16 x 64) gathered from x / mean / std
#pragma unroll
        for (int r = 0; r < 4; r++) {
            int kk = akk0 + 4*r;
            int cg = k0 + kk;
            const float* src;
            int cl;
            if (cg < Cc)            { src = x;      cl = cg; }
            else if (cg < 2*Cc)     { src = g_mean; cl = cg - Cc; }
            else                    { src = g_std;  cl = cg - 2*Cc; }
            As[kk][acol] = src[((size_t)b*Cc + cl)*(size_t)Tt + t0 + acol];
        }
        __syncthreads();
#pragma unroll
        for (int kk = 0; kk < BK; kk++) {
            float af[8], bf[4];
#pragma unroll
            for (int i = 0; i < 8; i++) af[i] = Ws[kk][ty*8 + i];
#pragma unroll
            for (int j = 0; j < 4; j++) bf[j] = As[kk][tx*4 + j];
#pragma unroll
            for (int i = 0; i < 8; i++)
#pragma unroll
                for (int j = 0; j < 4; j++)
                    acc[i][j] += af[i] * bf[j];
        }
        __syncthreads();
    }

    // Epilogue: tanh, multiply by W2, reduce over A
    float part[4] = {0.f, 0.f, 0.f, 0.f};
#pragma unroll
    for (int i = 0; i < 8; i++) {
        int a = ty*8 + i;
        float bb = b1[a];
        float w2 = W2[a];
#pragma unroll
        for (int j = 0; j < 4; j++) {
            float h = tanhf(acc[i][j] + bb);
            part[j] += w2 * h;
        }
    }
#pragma unroll
    for (int j = 0; j < 4; j++) red[ty][tx*4 + j] = part[j];
    __syncthreads();
    if (tid < BN) {
        float s = 0.f;
#pragma unroll
        for (int i = 0; i < 16; i++) s += red[i][tid];
        g_logits[b*Tt + t0 + tid] = s + b2[0];
    }
}

// ---------------- Kernel 3: per-batch max, e = exp(l - max), Z = cumsum(e) ----------------
__global__ void __launch_bounds__(256) softmax_kernel()
{
    int b = blockIdx.x;
    __shared__ float ls[Tt];
    __shared__ float ws[8];
    __shared__ float red[8];
    int tid = threadIdx.x;
    int lane = tid & 31, warp = tid >> 5;

    float mx = -3.4e38f;
    for (int i = tid; i < Tt; i += 256) {
        float v = g_logits[b*Tt + i];
        ls[i] = v;
        mx = fmaxf(mx, v);
    }
#pragma unroll
    for (int d = 16; d; d >>= 1) mx = fmaxf(mx, __shfl_xor_sync(0xffffffffu, mx, d));
    if (lane == 0) red[warp] = mx;
    __syncthreads();
    if (tid == 0) {
        float m = red[0];
        for (int i = 1; i < 8; i++) m = fmaxf(m, red[i]);
        red[0] = m;
    }
    __syncthreads();
    mx = red[0];

    int base = tid * 16;
    float ev[16], l1[16];
    float c1 = 0.f;
#pragma unroll
    for (int j = 0; j < 16; j++) {
        float e = expf(ls[base + j] - mx);
        ev[j] = e; c1 += e; l1[j] = c1;
    }
    float o1 = block_excl_scan256(c1, ws);
    float4* e4 = (float4*)(g_e + b*Tt + base);
    float4* z4 = (float4*)(g_Z + b*Tt + base);
#pragma unroll
    for (int q = 0; q < 4; q++) {
        e4[q] = make_float4(ev[q*4], ev[q*4+1], ev[q*4+2], ev[q*4+3]);
        z4[q] = make_float4(o1+l1[q*4], o1+l1[q*4+1], o1+l1[q*4+2], o1+l1[q*4+3]);
    }
}

// ---------------- Kernel 4: weighted mean/std pooling + final reduce ----------------
__global__ void __launch_bounds__(256) pool_kernel(const float* __restrict__ x,
                                                   float* __restrict__ out)
{
    int c = blockIdx.x, b = blockIdx.y;
    size_t roff = ((size_t)b*Cc + c)*(size_t)Tt;
    int tid = threadIdx.x;
    __shared__ float ws[8];
    __shared__ float red[8];
    int lane = tid & 31, warp = tid >> 5;

    const float4* x4 = (const float4*)(x + roff);
    const float4* e4 = (const float4*)(g_e + b*Tt);
    const float4* z4 = (const float4*)(g_Z + b*Tt);

    float xv[16], ev[16], zv[16];
#pragma unroll
    for (int q = 0; q < 4; q++) {
        float4 f = x4[tid*4 + q]; xv[q*4]=f.x; xv[q*4+1]=f.y; xv[q*4+2]=f.z; xv[q*4+3]=f.w;
        f = e4[tid*4 + q];        ev[q*4]=f.x; ev[q*4+1]=f.y; ev[q*4+2]=f.z; ev[q*4+3]=f.w;
        f = z4[tid*4 + q];        zv[q*4]=f.x; zv[q*4+1]=f.y; zv[q*4+2]=f.z; zv[q*4+3]=f.w;
    }

    float l1[16];
    float c1 = 0.f;
#pragma unroll
    for (int j = 0; j < 16; j++) { c1 += ev[j]*xv[j]; l1[j] = c1; }
    float o1 = block_excl_scan256(c1, ws);

    float sum_wm = 0.f, sum_ws = 0.f;
    float l2[16];
    float c2 = 0.f;
#pragma unroll
    for (int j = 0; j < 16; j++) {
        float wm = (o1 + l1[j]) / zv[j];
        sum_wm += wm;
        float d = xv[j] - wm;
        c2 += ev[j]*d*d;
        l2[j] = c2;
    }
    float o2 = block_excl_scan256(c2, ws);
#pragma unroll
    for (int j = 0; j < 16; j++) {
        float wv = (o2 + l2[j]) / zv[j];
        sum_ws += sqrtf(fmaxf(wv, 1e-12f));
    }

#pragma unroll
    for (int d = 16; d; d >>= 1) {
        sum_wm += __shfl_xor_sync(0xffffffffu, sum_wm, d);
        sum_ws += __shfl_xor_sync(0xffffffffu, sum_ws, d);
    }
    if (lane == 0) red[warp] = sum_wm;
    __syncthreads();
    if (tid == 0) {
        float tot_m = 0.f;
        for (int i = 0; i < 8; i++) tot_m += red[i];
        red[0] = tot_m;
    }
    __syncthreads();
    float tot_m = red[0];
    __syncthreads();
    if (lane == 0) red[warp] = sum_ws;
    __syncthreads();
    if (tid == 0) {
        float tot_s = 0.f;
        for (int i = 0; i < 8; i++) tot_s += red[i];
        const float fw = (float)(1.0 / (4096.0 + 1e-12));
        out[(size_t)b*(2*Cc) + c]      = tot_m * fw;
        out[(size_t)b*(2*Cc) + Cc + c] = tot_s * fw;
    }
}

extern "C" void kernel_launch(void* const* d_in, const int* in_sizes, int n_in,
                              void* d_out, int out_size)
{
    const float* x       = (const float*)d_in[0];
    const void*  lengths = d_in[1];            // int32 or int64, auto-detected
    const float* W1      = (const float*)d_in[2];
    const float* b1      = (const float*)d_in[3];
    const float* W2      = (const float*)d_in[4];
    const float* b2      = (const float*)d_in[5];
    float* out = (float*)d_out;

    dim3 gs(Cc, Bb);
    stats_kernel<<<gs, 256>>>(x, lengths);
    dim3 gl(Tt / BN, Bb);
    logits_kernel<<<gl, 256>>>(x, W1, b1, W2, b2);
    softmax_kernel<<<Bb, 256>>>();
    pool_kernel<<<gs, 256>>>(x, out);
}

// round 5
// speedup vs baseline: 2.9737x; 2.9737x over previous
#include <cuda_runtime.h>
#include <math.h>
#include <stdint.h>

#define Bb 8
#define Cc 1536
#define Tt 4096
#define Aa 128
#define K3 (3*Cc)   // 4608

// ---- warp-MMA logits GEMM config ----
#define BKC 32              // K per chunk
#define NCH (K3/BKC)        // 144
#define A_STR 36            // W1 tile [128 a][k] stride (conflict-free frags)
#define B_STR 136           // attn tile [32 k][t] stride (conflict-free frags)

// Scratch (allocation-free rule: __device__ globals)
static __device__ float g_mean[(size_t)Bb*Cc*Tt];
static __device__ float g_std [(size_t)Bb*Cc*Tt];
static __device__ float g_logits[Bb*Tt];
static __device__ float g_e[Bb*Tt];
static __device__ float g_Z[Bb*Tt];

__device__ __forceinline__ float f2tf32(float f) {
    uint32_t r;
    asm("cvt.rna.tf32.f32 %0, %1;" : "=r"(r) : "f"(f));
    return __uint_as_float(r);
}

__device__ __forceinline__ void mma_tf32(float* d, const float* a, const float* b)
{
    asm volatile(
        "mma.sync.aligned.m16n8k8.row.col.f32.tf32.tf32.f32 "
        "{%0,%1,%2,%3}, {%4,%5,%6,%7}, {%8,%9}, {%0,%1,%2,%3};"
        : "+f"(d[0]), "+f"(d[1]), "+f"(d[2]), "+f"(d[3])
        : "r"(__float_as_uint(a[0])), "r"(__float_as_uint(a[1])),
          "r"(__float_as_uint(a[2])), "r"(__float_as_uint(a[3])),
          "r"(__float_as_uint(b[0])), "r"(__float_as_uint(b[1])));
}

// Robust lengths read (reference declares int64; JAX w/o x64 emits int32).
__device__ __forceinline__ int load_length(const void* lp, int b)
{
    const int* w = (const int*)lp;
    bool is64 = true;
#pragma unroll
    for (int i = 0; i < 4; i++)
        if (w[2*i + 1] != 0) is64 = false;
    if (is64) return (int)((const long long*)lp)[b];
    return w[b];
}

// Exclusive block scan over 256 per-thread values.
__device__ __forceinline__ float block_excl_scan256(float v, float* ws)
{
    int lane = threadIdx.x & 31;
    int warp = threadIdx.x >> 5;
    float incl = v;
#pragma unroll
    for (int d = 1; d < 32; d <<= 1) {
        float n = __shfl_up_sync(0xffffffffu, incl, d);
        if (lane >= d) incl += n;
    }
    __syncthreads();
    if (lane == 31) ws[warp] = incl;
    __syncthreads();
    if (warp == 0) {
        float wv = (lane < 8) ? ws[lane] : 0.f;
        float wi = wv;
#pragma unroll
        for (int d = 1; d < 8; d <<= 1) {
            float n = __shfl_up_sync(0xffffffffu, wi, d);
            if (lane >= d) wi += n;
        }
        if (lane < 8) ws[lane] = wi - wv;
    }
    __syncthreads();
    return ws[warp] + (incl - v);
}

// ---------------- Kernel 1: causal mean / std ----------------
__global__ void __launch_bounds__(256) stats_kernel(const float* __restrict__ x,
                                                    const void* __restrict__ lengths)
{
    int c = blockIdx.x, b = blockIdx.y;
    size_t roff = ((size_t)b*Cc + c)*(size_t)Tt;
    const float4* row4 = (const float4*)(x + roff);
    float4* m4 = (float4*)(g_mean + roff);
    float4* s4 = (float4*)(g_std  + roff);
    int len = load_length(lengths, b);
    __shared__ float ws[8];
    int tid = threadIdx.x;
    int base = tid * 16;

    float xv[16];
#pragma unroll
    for (int q = 0; q < 4; q++) {
        float4 f = row4[tid*4 + q];
        xv[q*4+0]=f.x; xv[q*4+1]=f.y; xv[q*4+2]=f.z; xv[q*4+3]=f.w;
    }
    float l1[16], l2[16];
    float c1 = 0.f, c2 = 0.f;
#pragma unroll
    for (int j = 0; j < 16; j++) {
        int t = base + j;
        float v = (t < len) ? xv[j] : 0.f;
        c1 += v; c2 += v*v;
        l1[j] = c1; l2[j] = c2;
    }
    float o1 = block_excl_scan256(c1, ws);
    float o2 = block_excl_scan256(c2, ws);

    float mv[16], sv[16];
#pragma unroll
    for (int j = 0; j < 16; j++) {
        int t = base + j;
        int cn = (t + 1 < len) ? (t + 1) : len;
        float cnt = (cn < 1) ? 1.f : (float)cn;
        float m = (o1 + l1[j]) / cnt;
        float var = (o2 + l2[j]) / cnt - m*m;
        mv[j] = m;
        sv[j] = sqrtf(fmaxf(var, 1e-12f));
    }
#pragma unroll
    for (int q = 0; q < 4; q++) {
        m4[tid*4+q] = make_float4(mv[q*4], mv[q*4+1], mv[q*4+2], mv[q*4+3]);
        s4[tid*4+q] = make_float4(sv[q*4], sv[q*4+1], sv[q*4+2], sv[q*4+3]);
    }
}

// ---------------- Kernel 2: logits via warp-level TF32 MMA ----------------
// D[a=128][t=128] = W1[a,k] . attn[k,t]; warp grid 4(a) x 2(t), warp tile 32x64.
__global__ void __launch_bounds__(256, 2) logits_mma_kernel(const float* __restrict__ x,
                                                            const float* __restrict__ W1,
                                                            const float* __restrict__ b1,
                                                            const float* __restrict__ W2,
                                                            const float* __restrict__ b2)
{
    __shared__ float As[128 * A_STR];   // W1 tile, [a][k] stride 36  (18432 B)
    __shared__ float Bs[BKC * B_STR];   // attn tile, [k][t] stride 136 (17408 B)
    __shared__ float red[4][128];

    int tid  = threadIdx.x;
    int lane = tid & 31;
    int wid  = tid >> 5;
    int g    = lane >> 2;     // group 0..7
    int tig  = lane & 3;      // thread-in-group
    int wm   = wid >> 1;      // a quadrant 0..3
    int wn   = wid & 1;       // t half 0..1
    int b    = blockIdx.y;
    int t0   = blockIdx.x * 128;

    // Producer mappings
    int pa  = tid >> 1;            // W1: a row
    int pkh = (tid & 1) * 16;      // W1: k half
    int pk  = tid >> 3;            // attn: k row 0..31
    int pt8 = tid & 7;             // attn: t float4 lane

    float acc[2][8][4];
#pragma unroll
    for (int mi = 0; mi < 2; mi++)
#pragma unroll
        for (int ni = 0; ni < 8; ni++)
#pragma unroll
            for (int r = 0; r < 4; r++) acc[mi][ni][r] = 0.f;

    float4 ast[4];   // attn staging (prefetch)

    // attn source for chunk ch (k0 = ch*32; 1536 % 32 == 0 so source is uniform)
    auto stage_attn = [&](int ch) {
        int k0 = ch * BKC;
        const float* src; int crow;
        if (k0 < Cc)        { src = x;      crow = k0; }
        else if (k0 < 2*Cc) { src = g_mean; crow = k0 - Cc; }
        else                { src = g_std;  crow = k0 - 2*Cc; }
        const float4* arow = (const float4*)(src + ((size_t)b*Cc + crow + pk)*(size_t)Tt + t0);
#pragma unroll
        for (int q = 0; q < 4; q++) ast[q] = __ldg(arow + pt8 + q*8);
    };

    stage_attn(0);

    for (int ch = 0; ch < NCH; ch++) {
        int k0 = ch * BKC;
        // W1 loads (L2-resident after first wave)
        float4 wv[4];
        const float4* wrow = (const float4*)(W1 + (size_t)pa*K3 + k0 + pkh);
#pragma unroll
        for (int q = 0; q < 4; q++) wv[q] = __ldg(wrow + q);

        __syncthreads();   // consumers done with previous tiles

        // store attn staging -> Bs (tf32-rounded)
#pragma unroll
        for (int q = 0; q < 4; q++) {
            float* d = &Bs[pk*B_STR + (pt8 + q*8)*4];
            d[0] = f2tf32(ast[q].x); d[1] = f2tf32(ast[q].y);
            d[2] = f2tf32(ast[q].z); d[3] = f2tf32(ast[q].w);
        }
        // store W1 -> As
#pragma unroll
        for (int q = 0; q < 4; q++) {
            float* d = &As[pa*A_STR + pkh + q*4];
            d[0] = f2tf32(wv[q].x); d[1] = f2tf32(wv[q].y);
            d[2] = f2tf32(wv[q].z); d[3] = f2tf32(wv[q].w);
        }
        __syncthreads();

        if (ch + 1 < NCH) stage_attn(ch + 1);   // prefetch overlaps compute

#pragma unroll
        for (int ks = 0; ks < 4; ks++) {
            int kb = ks * 8;
            float a_fr[2][4];
#pragma unroll
            for (int mi = 0; mi < 2; mi++) {
                int ar = wm*32 + mi*16;
                a_fr[mi][0] = As[(ar + g    )*A_STR + kb + tig];
                a_fr[mi][1] = As[(ar + 8 + g)*A_STR + kb + tig];
                a_fr[mi][2] = As[(ar + g    )*A_STR + kb + tig + 4];
                a_fr[mi][3] = As[(ar + 8 + g)*A_STR + kb + tig + 4];
            }
            float b_fr[8][2];
#pragma unroll
            for (int ni = 0; ni < 8; ni++) {
                int t = wn*64 + ni*8 + g;
                b_fr[ni][0] = Bs[(kb + tig    )*B_STR + t];
                b_fr[ni][1] = Bs[(kb + tig + 4)*B_STR + t];
            }
#pragma unroll
            for (int mi = 0; mi < 2; mi++)
#pragma unroll
                for (int ni = 0; ni < 8; ni++)
                    mma_tf32(acc[mi][ni], a_fr[mi], b_fr[ni]);
        }
    }

    // Epilogue: tanh + W2 dot over a, reduce to logits[t]
    float part[16];
#pragma unroll
    for (int i = 0; i < 16; i++) part[i] = 0.f;
#pragma unroll
    for (int mi = 0; mi < 2; mi++) {
        int abase = wm*32 + mi*16;
        float b1a = __ldg(b1 + abase + g),     w2a = __ldg(W2 + abase + g);
        float b1b = __ldg(b1 + abase + 8 + g), w2b = __ldg(W2 + abase + 8 + g);
#pragma unroll
        for (int ni = 0; ni < 8; ni++) {
            part[ni*2+0] += w2a*tanhf(acc[mi][ni][0] + b1a) + w2b*tanhf(acc[mi][ni][2] + b1b);
            part[ni*2+1] += w2a*tanhf(acc[mi][ni][1] + b1a) + w2b*tanhf(acc[mi][ni][3] + b1b);
        }
    }
    // reduce over the 8 groups (lanes sharing the same t)
#pragma unroll
    for (int o = 4; o <= 16; o <<= 1)
#pragma unroll
        for (int i = 0; i < 16; i++)
            part[i] += __shfl_xor_sync(0xffffffffu, part[i], o);
    if (lane < 4) {
#pragma unroll
        for (int ni = 0; ni < 8; ni++) {
            red[wm][wn*64 + ni*8 + lane*2 + 0] = part[ni*2+0];
            red[wm][wn*64 + ni*8 + lane*2 + 1] = part[ni*2+1];
        }
    }
    __syncthreads();
    if (tid < 128) {
        float s = red[0][tid] + red[1][tid] + red[2][tid] + red[3][tid];
        g_logits[b*Tt + t0 + tid] = s + __ldg(b2);
    }
}

// ---------------- Kernel 3: per-batch max, e = exp(l - max), Z = cumsum(e) ----------------
__global__ void __launch_bounds__(256) softmax_kernel()
{
    int b = blockIdx.x;
    __shared__ float ls[Tt];
    __shared__ float ws[8];
    __shared__ float red[8];
    int tid = threadIdx.x;
    int lane = tid & 31, warp = tid >> 5;

    float mx = -3.4e38f;
    for (int i = tid; i < Tt; i += 256) {
        float v = g_logits[b*Tt + i];
        ls[i] = v;
        mx = fmaxf(mx, v);
    }
#pragma unroll
    for (int d = 16; d; d >>= 1) mx = fmaxf(mx, __shfl_xor_sync(0xffffffffu, mx, d));
    if (lane == 0) red[warp] = mx;
    __syncthreads();
    if (tid == 0) {
        float m = red[0];
        for (int i = 1; i < 8; i++) m = fmaxf(m, red[i]);
        red[0] = m;
    }
    __syncthreads();
    mx = red[0];

    int base = tid * 16;
    float ev[16], l1[16];
    float c1 = 0.f;
#pragma unroll
    for (int j = 0; j < 16; j++) {
        float e = expf(ls[base + j] - mx);
        ev[j] = e; c1 += e; l1[j] = c1;
    }
    float o1 = block_excl_scan256(c1, ws);
    float4* e4 = (float4*)(g_e + b*Tt + base);
    float4* z4 = (float4*)(g_Z + b*Tt + base);
#pragma unroll
    for (int q = 0; q < 4; q++) {
        e4[q] = make_float4(ev[q*4], ev[q*4+1], ev[q*4+2], ev[q*4+3]);
        z4[q] = make_float4(o1+l1[q*4], o1+l1[q*4+1], o1+l1[q*4+2], o1+l1[q*4+3]);
    }
}

// ---------------- Kernel 4: weighted mean/std pooling + final reduce ----------------
__global__ void __launch_bounds__(256) pool_kernel(const float* __restrict__ x,
                                                   float* __restrict__ out)
{
    int c = blockIdx.x, b = blockIdx.y;
    size_t roff = ((size_t)b*Cc + c)*(size_t)Tt;
    int tid = threadIdx.x;
    __shared__ float ws[8];
    __shared__ float red[8];
    int lane = tid & 31, warp = tid >> 5;

    const float4* x4 = (const float4*)(x + roff);
    const float4* e4 = (const float4*)(g_e + b*Tt);
    const float4* z4 = (const float4*)(g_Z + b*Tt);

    float xv[16], ev[16], zv[16];
#pragma unroll
    for (int q = 0; q < 4; q++) {
        float4 f = x4[tid*4 + q]; xv[q*4]=f.x; xv[q*4+1]=f.y; xv[q*4+2]=f.z; xv[q*4+3]=f.w;
        f = e4[tid*4 + q];        ev[q*4]=f.x; ev[q*4+1]=f.y; ev[q*4+2]=f.z; ev[q*4+3]=f.w;
        f = z4[tid*4 + q];        zv[q*4]=f.x; zv[q*4+1]=f.y; zv[q*4+2]=f.z; zv[q*4+3]=f.w;
    }

    float l1[16];
    float c1 = 0.f;
#pragma unroll
    for (int j = 0; j < 16; j++) { c1 += ev[j]*xv[j]; l1[j] = c1; }
    float o1 = block_excl_scan256(c1, ws);

    float sum_wm = 0.f, sum_ws = 0.f;
    float l2[16];
    float c2 = 0.f;
#pragma unroll
    for (int j = 0; j < 16; j++) {
        float wm = (o1 + l1[j]) / zv[j];
        sum_wm += wm;
        float d = xv[j] - wm;
        c2 += ev[j]*d*d;
        l2[j] = c2;
    }
    float o2 = block_excl_scan256(c2, ws);
#pragma unroll
    for (int j = 0; j < 16; j++) {
        float wv = (o2 + l2[j]) / zv[j];
        sum_ws += sqrtf(fmaxf(wv, 1e-12f));
    }

#pragma unroll
    for (int d = 16; d; d >>= 1) {
        sum_wm += __shfl_xor_sync(0xffffffffu, sum_wm, d);
        sum_ws += __shfl_xor_sync(0xffffffffu, sum_ws, d);
    }
    if (lane == 0) red[warp] = sum_wm;
    __syncthreads();
    if (tid == 0) {
        float tot_m = 0.f;
        for (int i = 0; i < 8; i++) tot_m += red[i];
        red[0] = tot_m;
    }
    __syncthreads();
    float tot_m = red[0];
    __syncthreads();
    if (lane == 0) red[warp] = sum_ws;
    __syncthreads();
    if (tid == 0) {
        float tot_s = 0.f;
        for (int i = 0; i < 8; i++) tot_s += red[i];
        const float fw = (float)(1.0 / (4096.0 + 1e-12));
        out[(size_t)b*(2*Cc) + c]      = tot_m * fw;
        out[(size_t)b*(2*Cc) + Cc + c] = tot_s * fw;
    }
}

extern "C" void kernel_launch(void* const* d_in, const int* in_sizes, int n_in,
                              void* d_out, int out_size)
{
    const float* x       = (const float*)d_in[0];
    const void*  lengths = d_in[1];            // int32 or int64, auto-detected
    const float* W1      = (const float*)d_in[2];
    const float* b1      = (const float*)d_in[3];
    const float* W2      = (const float*)d_in[4];
    const float* b2      = (const float*)d_in[5];
    float* out = (float*)d_out;

    dim3 gs(Cc, Bb);
    stats_kernel<<<gs, 256>>>(x, lengths);
    dim3 gl(Tt / 128, Bb);
    logits_mma_kernel<<<gl, 256>>>(x, W1, b1, W2, b2);
    softmax_kernel<<<Bb, 256>>>();
    pool_kernel<<<gs, 256>>>(x, out);
}